// round 14
// baseline (speedup 1.0000x reference)
#include <cuda_runtime.h>
#include <cuda_bf16.h>
#include <cstdint>

#define Bn 256
#define Ln 1024
#define En 128
#define Hn 256
#define Vn 64
#define NB 8                  // batches per cluster (MMA N)
#define NCLUS (Bn / NB)       // 32 clusters of 2 CTAs = 64 CTAs

// ---- device-global scratch (no allocations allowed) ----
__device__ float g_proj[Vn * Hn];                    // token -> x_proj row (b_e folded in)
__device__ float g_hout[(size_t)Bn * Ln * Hn];       // all hidden states, 268MB
__device__ int   g_x_is32;

__device__ __forceinline__ float tanh_hw(float x) {
    float r;
    asm("tanh.approx.f32 %0, %1;" : "=f"(r) : "f"(x));
    return r;
}
__device__ __forceinline__ uint32_t f2tf32(float f) {
    uint32_t u;
    asm("cvt.rna.tf32.f32 %0, %1;" : "=r"(u) : "f"(f));
    return u;
}
__device__ __forceinline__ uint32_t smem_u32(const void* p) {
    uint32_t a;
    asm("{ .reg .u64 t; cvta.to.shared.u64 t, %1; cvt.u32.u64 %0, t; }" : "=r"(a) : "l"(p));
    return a;
}
__device__ __forceinline__ uint32_t mapa_peer(uint32_t laddr, uint32_t rank) {
    uint32_t r;
    asm("mapa.shared::cluster.u32 %0, %1, %2;" : "=r"(r) : "r"(laddr), "r"(rank));
    return r;
}

// ---------------- dtype detection ----------------
__global__ void k_reset() { g_x_is32 = 0; }

__global__ void k_detect(const unsigned int* __restrict__ xw) {
    int i = blockIdx.x * blockDim.x + threadIdx.x;
    int idx = 2 * i + 1;
    if (idx < Bn * Ln) {
        if (xw[idx] != 0u) g_x_is32 = 1;   // int64 high halves all zero (vals 0..63)
    }
}

// ---------------- projection table ----------------
__global__ void k_proj(const float* __restrict__ emb, const float* __restrict__ We,
                       const float* __restrict__ be) {
    __shared__ float es[En];
    int v = blockIdx.x, j = threadIdx.x;
    if (j < En) es[j] = emb[v * En + j];
    __syncthreads();
    float acc = 0.f;
    #pragma unroll
    for (int e = 0; e < En; e++) acc = fmaf(es[e], We[j * En + e], acc);
    g_proj[v * Hn + j] = acc + be[j];
}

// ---------------- recurrence: HMMA + 2-CTA cluster M-split ----------------
// 64 CTAs (32 clusters x 2) x 256 threads (8 warps). Cluster owns batches
// [8c, 8c+8); CTA rank r owns m-rows [128r, 128r+128) -> 128 HMMA/step/SM
// (halved dispatch floor). h (full 256 rows) double-buffered in EACH CTA's
// smem in B-fragment layout; each step every CTA stores its 128 rows locally
// AND into the peer via st.shared::cluster, then fence + one remote mbarrier
// arrive; peer waits with acquire.cluster parity wait. No cluster.sync in the
// loop (keeps g_proj L1-resident).

__device__ __forceinline__ uint32_t b_addr(int j, int n) {
    return (uint32_t)((j >> 4) * 256 + (((n << 2) | ((j & 7) >> 1)) << 3)
                      + (((j >> 3) & 1) << 2) + ((j & 1) << 1));
}
__device__ __forceinline__ unsigned bf2(float a, float b) {
    __nv_bfloat162 t = __floats2bfloat162_rn(a, b);
    return *(unsigned*)&t;
}
__device__ __forceinline__ unsigned short bf1(float a) {
    __nv_bfloat16 t = __float2bfloat16_rn(a);
    return *(unsigned short*)&t;
}

__global__ void __launch_bounds__(256, 1) __cluster_dims__(2, 1, 1)
k_rnn(const void* __restrict__ xraw,
      const float* __restrict__ hidden, const float* __restrict__ Wh,
      const float* __restrict__ bh, float* __restrict__ dout, int write_final) {
    __shared__ __align__(16) char bbuf[2][4096];
    __shared__ __align__(8) unsigned long long mbar[1];
    const int tid = threadIdx.x;
    const int wid = tid >> 5, lane = tid & 31;
    const int g = lane >> 2, tt = lane & 3;
    uint32_t rank;
    asm("mov.u32 %0, %%cluster_ctarank;" : "=r"(rank));
    const int j0 = (int)rank * 128 + wid * 16 + g, j1 = j0 + 8;  // my two rows
    const int n0 = 2 * tt, n1 = n0 + 1;                          // my two batches
    const int B0 = (blockIdx.x >> 1) * NB;
    const int is32 = g_x_is32;
    const int* x32       = (const int*)xraw;
    const long long* x64 = (const long long*)xraw;

    const uint32_t mb = smem_u32(mbar);
    const uint32_t bb0 = smem_u32(bbuf);
    const uint32_t peer_mb   = mapa_peer(mb, rank ^ 1u);
    const uint32_t peer_bbuf = mapa_peer(bb0, rank ^ 1u);

    // ---- W_h rows -> A fragments in registers ----
    unsigned wf[16][4];
    #pragma unroll
    for (int kk = 0; kk < 16; kk++) {
        int k = kk * 16 + 2 * tt;
        float2 p0 = *(const float2*)(Wh + j0 * Hn + k);
        float2 p1 = *(const float2*)(Wh + j1 * Hn + k);
        float2 p2 = *(const float2*)(Wh + j0 * Hn + k + 8);
        float2 p3 = *(const float2*)(Wh + j1 * Hn + k + 8);
        wf[kk][0] = bf2(p0.x, p0.y);
        wf[kk][1] = bf2(p1.x, p1.y);
        wf[kk][2] = bf2(p2.x, p2.y);
        wf[kk][3] = bf2(p3.x, p3.y);
    }

    // ---- full initial h (all 256 rows) into local bbuf[0] ----
    for (int p = tid; p < Hn * NB; p += 256) {
        int j = p >> 3, n = p & 7;
        float hv = hidden[(B0 + n) * Hn + j];
        *(__nv_bfloat16*)(bbuf[0] + b_addr(j, n)) = __float2bfloat16_rn(hv);
    }

    if (tid == 0)
        asm volatile("mbarrier.init.shared.b64 [%0], 1;" :: "r"(mb) : "memory");
    __syncthreads();
    // both CTAs: mbar init + initial fill visible before any remote traffic
    asm volatile("barrier.cluster.arrive.aligned;" ::: "memory");
    asm volatile("barrier.cluster.wait.aligned;" ::: "memory");

    const float bh0 = bh[j0], bh1 = bh[j1];
    size_t base = ((size_t)(B0 + n0) * Ln) * Hn + j0;
    const size_t NSTRIDE = (size_t)Ln * Hn;

    int tokA = is32 ? x32[(B0 + n0) * Ln] : (int)x64[(B0 + n0) * Ln];
    int tokB = is32 ? x32[(B0 + n1) * Ln] : (int)x64[(B0 + n1) * Ln];

    float h00 = 0.f, h01 = 0.f, h10 = 0.f, h11 = 0.f;
    for (int t = 0; t < Ln; t++) {
        if (t > 0) {
            // wait for peer's h_{t-1} (acquire at cluster scope)
            uint32_t ph = (uint32_t)((t - 1) & 1);
            uint32_t done;
            asm volatile("{\n\t.reg .pred p;\n\t"
                "mbarrier.try_wait.parity.acquire.cluster.shared::cta.b64 p, [%1], %2;\n\t"
                "selp.b32 %0, 1, 0, p;\n\t}" : "=r"(done) : "r"(mb), "r"(ph) : "memory");
            if (!done) {
                asm volatile("{\n\t.reg .pred P1;\n\t"
                    "WL_%=:\n\t"
                    "mbarrier.try_wait.parity.acquire.cluster.shared::cta.b64 P1, [%0], %1, 0x989680;\n\t"
                    "@P1 bra.uni WD_%=;\n\tbra.uni WL_%=;\n\tWD_%=:\n\t}"
                    :: "r"(mb), "r"(ph) : "memory");
            }
        }

        float xp00 = g_proj[tokA * Hn + j0];
        float xp01 = g_proj[tokB * Hn + j0];
        float xp10 = g_proj[tokA * Hn + j1];
        float xp11 = g_proj[tokB * Hn + j1];

        if (t + 1 < Ln) {
            tokA = is32 ? x32[(B0 + n0) * Ln + t + 1] : (int)x64[(B0 + n0) * Ln + t + 1];
            tokB = is32 ? x32[(B0 + n1) * Ln + t + 1] : (int)x64[(B0 + n1) * Ln + t + 1];
        }

        float c0 = 0.f, c1 = 0.f, c2 = 0.f, c3 = 0.f;
        const char* cb = bbuf[t & 1];
        #pragma unroll
        for (int kk = 0; kk < 16; kk++) {
            unsigned long long bbv = *(const unsigned long long*)(cb + kk * 256 + lane * 8);
            unsigned b0 = (unsigned)bbv, b1 = (unsigned)(bbv >> 32);
            asm volatile(
                "mma.sync.aligned.m16n8k16.row.col.f32.bf16.bf16.f32 "
                "{%0,%1,%2,%3}, {%4,%5,%6,%7}, {%8,%9}, {%0,%1,%2,%3};"
                : "+f"(c0), "+f"(c1), "+f"(c2), "+f"(c3)
                : "r"(wf[kk][0]), "r"(wf[kk][1]), "r"(wf[kk][2]), "r"(wf[kk][3]),
                  "r"(b0), "r"(b1));
        }

        h00 = tanh_hw(c0 + xp00 + bh0);
        h01 = tanh_hw(c1 + xp01 + bh0);
        h10 = tanh_hw(c2 + xp10 + bh1);
        h11 = tanh_hw(c3 + xp11 + bh1);

        // next-step B operand: local + peer (my 2 rows x 2 batches)
        const uint32_t nxt = (uint32_t)(((t & 1) ^ 1) * 4096);
        uint32_t a00 = b_addr(j0, n0), a01 = b_addr(j0, n1);
        uint32_t a10 = b_addr(j1, n0), a11 = b_addr(j1, n1);
        unsigned short v00 = bf1(h00), v01 = bf1(h01), v10 = bf1(h10), v11 = bf1(h11);
        *(unsigned short*)(bbuf[0] + nxt + a00) = v00;
        *(unsigned short*)(bbuf[0] + nxt + a01) = v01;
        *(unsigned short*)(bbuf[0] + nxt + a10) = v10;
        *(unsigned short*)(bbuf[0] + nxt + a11) = v11;
        if (t + 1 < Ln) {
            uint32_t pb = peer_bbuf + nxt;
            asm volatile("st.shared::cluster.u16 [%0], %1;" :: "r"(pb + a00), "h"(v00) : "memory");
            asm volatile("st.shared::cluster.u16 [%0], %1;" :: "r"(pb + a01), "h"(v01) : "memory");
            asm volatile("st.shared::cluster.u16 [%0], %1;" :: "r"(pb + a10), "h"(v10) : "memory");
            asm volatile("st.shared::cluster.u16 [%0], %1;" :: "r"(pb + a11), "h"(v11) : "memory");
        }

        // fp32 hidden states to gmem (off critical path)
        g_hout[base]               = h00;
        g_hout[base + NSTRIDE]     = h01;
        g_hout[base + 8]           = h10;
        g_hout[base + NSTRIDE + 8] = h11;
        base += Hn;

        if (t + 1 < Ln) {
            asm volatile("fence.acq_rel.cluster;" ::: "memory");
            __syncthreads();
            if (tid == 0)
                asm volatile("mbarrier.arrive.release.cluster.shared::cluster.b64 _, [%0];"
                             :: "r"(peer_mb) : "memory");
        } else {
            __syncthreads();
        }
    }

    if (write_final) {
        float* fh = dout + (size_t)Bn * Ln * Vn;
        fh[(B0 + n0) * Hn + j0] = h00;
        fh[(B0 + n1) * Hn + j0] = h01;
        fh[(B0 + n0) * Hn + j1] = h10;
        fh[(B0 + n1) * Hn + j1] = h11;
    }

    // no CTA may exit while peer remote stores could be in flight
    asm volatile("barrier.cluster.arrive.aligned;" ::: "memory");
    asm volatile("barrier.cluster.wait.aligned;" ::: "memory");
}

// ---------------- logits GEMM on tf32 HMMA (mma.sync m16n8k8) ----------------
#define FT_PAD 72
#define HS_PAD 260
#define LOG_SMEM (256 * FT_PAD * 4 + 64 * HS_PAD * 4)

__global__ void __launch_bounds__(256, 1) k_logits(const float* __restrict__ fcw,
        const float* __restrict__ fcb, float* __restrict__ out) {
    extern __shared__ char smem[];
    uint32_t* fT  = (uint32_t*)smem;                          // [256][72]
    uint32_t* hsm = (uint32_t*)(smem + 256 * FT_PAD * 4);     // [64][260]
    const int tid = threadIdx.x;
    const int wid = tid >> 5, lane = tid & 31;
    const int g = lane >> 2, tt = lane & 3;
    const int nb = wid * 8;

    for (int p = tid; p < Vn * Hn; p += 256) {
        int v = p >> 8, k = p & 255;
        fT[k * FT_PAD + v] = f2tf32(fcw[v * Hn + k]);
    }
    const float2 bias = make_float2(fcb[nb + 2 * tt], fcb[nb + 2 * tt + 1]);
    __syncthreads();

    const int ntiles = (Bn * Ln) / 64;      // 4096
    for (int tile = blockIdx.x; tile < ntiles; tile += gridDim.x) {
        const float4* src = (const float4*)(g_hout + (size_t)tile * 64 * Hn);
        for (int p = tid; p < 64 * 64; p += 256) {
            int row = p >> 6, kc = p & 63;
            float4 v = src[row * 64 + kc];
            uint4 u;
            u.x = f2tf32(v.x); u.y = f2tf32(v.y);
            u.z = f2tf32(v.z); u.w = f2tf32(v.w);
            *(uint4*)(hsm + row * HS_PAD + 4 * kc) = u;
        }
        __syncthreads();

        float c[4][4];
        #pragma unroll
        for (int mt = 0; mt < 4; mt++)
            #pragma unroll
            for (int e = 0; e < 4; e++) c[mt][e] = 0.f;

        #pragma unroll 4
        for (int ks = 0; ks < 32; ks++) {
            int k0 = 8 * ks;
            uint32_t b0 = fT[(k0 + tt) * FT_PAD + nb + g];
            uint32_t b1 = fT[(k0 + tt + 4) * FT_PAD + nb + g];
            #pragma unroll
            for (int mt = 0; mt < 4; mt++) {
                int r0 = mt * 16 + g;
                uint32_t a0 = hsm[r0 * HS_PAD + k0 + tt];
                uint32_t a1 = hsm[(r0 + 8) * HS_PAD + k0 + tt];
                uint32_t a2 = hsm[r0 * HS_PAD + k0 + tt + 4];
                uint32_t a3 = hsm[(r0 + 8) * HS_PAD + k0 + tt + 4];
                asm volatile(
                    "mma.sync.aligned.m16n8k8.row.col.f32.tf32.tf32.f32 "
                    "{%0,%1,%2,%3}, {%4,%5,%6,%7}, {%8,%9}, {%0,%1,%2,%3};"
                    : "+f"(c[mt][0]), "+f"(c[mt][1]), "+f"(c[mt][2]), "+f"(c[mt][3])
                    : "r"(a0), "r"(a1), "r"(a2), "r"(a3), "r"(b0), "r"(b1));
            }
        }

        #pragma unroll
        for (int mt = 0; mt < 4; mt++) {
            int r0 = mt * 16 + g;
            size_t o0 = ((size_t)tile * 64 + r0) * 64 + nb + 2 * tt;
            *(float2*)(out + o0) = make_float2(c[mt][0] + bias.x, c[mt][1] + bias.y);
            *(float2*)(out + o0 + 8 * 64) = make_float2(c[mt][2] + bias.x, c[mt][3] + bias.y);
        }
        __syncthreads();
    }
}

// ---------------- launch ----------------
extern "C" void kernel_launch(void* const* d_in, const int* in_sizes, int n_in,
                              void* d_out, int out_size) {
    const void*  x      = d_in[0];
    const float* hidden = (const float*)d_in[1];
    const float* emb    = (const float*)d_in[2];
    const float* We     = (const float*)d_in[3];
    const float* be     = (const float*)d_in[4];
    const float* Wh     = (const float*)d_in[5];
    const float* bhp    = (const float*)d_in[6];
    const float* fcw    = (const float*)d_in[7];
    const float* fcb    = (const float*)d_in[8];
    float* out = (float*)d_out;

    cudaFuncSetAttribute(k_logits, cudaFuncAttributeMaxDynamicSharedMemorySize, LOG_SMEM);

    k_reset<<<1, 1>>>();
    k_detect<<<(Bn * Ln / 2 + 255) / 256, 256>>>((const unsigned int*)x);
    k_proj<<<Vn, Hn>>>(emb, We, be);

    int write_final = (out_size >= Bn * Ln * Vn + Bn * Hn) ? 1 : 0;
    k_rnn<<<NCLUS * 2, 256>>>(x, hidden, Wh, bhp, out, write_final);
    k_logits<<<148, 256, LOG_SMEM>>>(fcw, fcb, out);
}

// round 15
// speedup vs baseline: 2.0877x; 2.0877x over previous
#include <cuda_runtime.h>
#include <cuda_fp16.h>
#include <cuda_bf16.h>
#include <cstdint>

#define Bn 256
#define Ln 1024
#define En 128
#define Hn 256
#define Vn 64
#define NB 8                  // batches per CTA (MMA N)
#define NCTA (Bn / NB)        // 32 CTAs

// ---- device-global scratch (no allocations allowed) ----
__device__ float  g_proj[Vn * Hn];                   // token -> x_proj row (b_e folded in)
__device__ __half g_hout[(size_t)Bn * Ln * Hn];      // all hidden states, fp16, 134MB
__device__ int    g_x_is32;

__device__ __forceinline__ float tanh_hw(float x) {
    float r;
    asm("tanh.approx.f32 %0, %1;" : "=f"(r) : "f"(x));
    return r;
}
__device__ __forceinline__ uint32_t smem_u32(const void* p) {
    uint32_t a;
    asm("{ .reg .u64 t; cvta.to.shared.u64 t, %1; cvt.u32.u64 %0, t; }" : "=r"(a) : "l"(p));
    return a;
}

// ---------------- dtype detection ----------------
__global__ void k_reset() { g_x_is32 = 0; }

__global__ void k_detect(const unsigned int* __restrict__ xw) {
    int i = blockIdx.x * blockDim.x + threadIdx.x;
    int idx = 2 * i + 1;
    if (idx < Bn * Ln) {
        if (xw[idx] != 0u) g_x_is32 = 1;   // int64 high halves all zero (vals 0..63)
    }
}

// ---------------- projection table ----------------
__global__ void k_proj(const float* __restrict__ emb, const float* __restrict__ We,
                       const float* __restrict__ be) {
    __shared__ float es[En];
    int v = blockIdx.x, j = threadIdx.x;
    if (j < En) es[j] = emb[v * En + j];
    __syncthreads();
    float acc = 0.f;
    #pragma unroll
    for (int e = 0; e < En; e++) acc = fmaf(es[e], We[j * En + e], acc);
    g_proj[v * Hn + j] = acc + be[j];
}

// ---------------- recurrence on HMMA (R12 structure, proven fastest) -------
// 32 CTAs x 512 threads (16 warps). CTA owns batches [8c, 8c+8) end-to-end.
// Warp w owns output rows [16w, 16w+16). W_h in registers as A fragments.
// h double-buffered in smem in exact B-fragment layout. Single accumulator
// chain (R13's split spilled at the 128-reg cap). tanh.approx epilogue.
// g_hout now fp16 (feeds the fp16 logits GEMM).

__device__ __forceinline__ uint32_t b_addr(int j, int n) {
    return (uint32_t)((j >> 4) * 256 + (((n << 2) | ((j & 7) >> 1)) << 3)
                      + (((j >> 3) & 1) << 2) + ((j & 1) << 1));
}
__device__ __forceinline__ unsigned bf2(float a, float b) {
    __nv_bfloat162 t = __floats2bfloat162_rn(a, b);
    return *(unsigned*)&t;
}

__global__ void __launch_bounds__(512, 1) k_rnn(const void* __restrict__ xraw,
        const float* __restrict__ hidden, const float* __restrict__ Wh,
        const float* __restrict__ bh, float* __restrict__ dout, int write_final) {
    __shared__ __align__(16) char bbuf[2][4096];
    const int tid = threadIdx.x;
    const int wid = tid >> 5, lane = tid & 31;
    const int g = lane >> 2, tt = lane & 3;
    const int j0 = wid * 16 + g, j1 = j0 + 8;   // my two output rows
    const int n0 = 2 * tt, n1 = n0 + 1;         // my two batch columns
    const int B0 = blockIdx.x * NB;
    const int is32 = g_x_is32;
    const int* x32       = (const int*)xraw;
    const long long* x64 = (const long long*)xraw;

    // ---- load W_h as A fragments into registers (one-time) ----
    unsigned wf[16][4];
    #pragma unroll
    for (int kk = 0; kk < 16; kk++) {
        int k = kk * 16 + 2 * tt;
        float2 p0 = *(const float2*)(Wh + j0 * Hn + k);
        float2 p1 = *(const float2*)(Wh + j1 * Hn + k);
        float2 p2 = *(const float2*)(Wh + j0 * Hn + k + 8);
        float2 p3 = *(const float2*)(Wh + j1 * Hn + k + 8);
        wf[kk][0] = bf2(p0.x, p0.y);
        wf[kk][1] = bf2(p1.x, p1.y);
        wf[kk][2] = bf2(p2.x, p2.y);
        wf[kk][3] = bf2(p3.x, p3.y);
    }

    // ---- initial B fill from hidden (fp32 -> bf16, fragment layout) ----
    for (int p = tid; p < Hn * NB; p += 512) {
        int j = p >> 3, n = p & 7;
        float hv = hidden[(B0 + n) * Hn + j];
        *(__nv_bfloat16*)(bbuf[0] + b_addr(j, n)) = __float2bfloat16_rn(hv);
    }

    const float bh0 = bh[j0], bh1 = bh[j1];

    size_t base = ((size_t)(B0 + n0) * Ln) * Hn + j0;
    const size_t NSTRIDE = (size_t)Ln * Hn;

    int tokA = is32 ? x32[(B0 + n0) * Ln] : (int)x64[(B0 + n0) * Ln];
    int tokB = is32 ? x32[(B0 + n1) * Ln] : (int)x64[(B0 + n1) * Ln];

    __syncthreads();

    float h00 = 0.f, h01 = 0.f, h10 = 0.f, h11 = 0.f;
    for (int t = 0; t < Ln; t++) {
        // seed accumulators with x_proj + b_h (xp loads overlap the MMA chain)
        float c0 = g_proj[tokA * Hn + j0] + bh0;   // (j0, n0)
        float c1 = g_proj[tokB * Hn + j0] + bh0;   // (j0, n1)
        float c2 = g_proj[tokA * Hn + j1] + bh1;   // (j1, n0)
        float c3 = g_proj[tokB * Hn + j1] + bh1;   // (j1, n1)

        if (t + 1 < Ln) {
            tokA = is32 ? x32[(B0 + n0) * Ln + t + 1] : (int)x64[(B0 + n0) * Ln + t + 1];
            tokB = is32 ? x32[(B0 + n1) * Ln + t + 1] : (int)x64[(B0 + n1) * Ln + t + 1];
        }

        const char* cb = bbuf[t & 1];
        #pragma unroll
        for (int kk = 0; kk < 16; kk++) {
            unsigned long long bb = *(const unsigned long long*)(cb + kk * 256 + lane * 8);
            unsigned b0 = (unsigned)bb, b1 = (unsigned)(bb >> 32);
            asm volatile(
                "mma.sync.aligned.m16n8k16.row.col.f32.bf16.bf16.f32 "
                "{%0,%1,%2,%3}, {%4,%5,%6,%7}, {%8,%9}, {%0,%1,%2,%3};"
                : "+f"(c0), "+f"(c1), "+f"(c2), "+f"(c3)
                : "r"(wf[kk][0]), "r"(wf[kk][1]), "r"(wf[kk][2]), "r"(wf[kk][3]),
                  "r"(b0), "r"(b1));
        }

        h00 = tanh_hw(c0);
        h01 = tanh_hw(c1);
        h10 = tanh_hw(c2);
        h11 = tanh_hw(c3);

        // fp16 hidden states to gmem
        g_hout[base]               = __float2half_rn(h00);
        g_hout[base + NSTRIDE]     = __float2half_rn(h01);
        g_hout[base + 8]           = __float2half_rn(h10);
        g_hout[base + NSTRIDE + 8] = __float2half_rn(h11);
        base += Hn;

        // bf16 h into the other buffer (next step's B operand)
        char* nb = bbuf[(t & 1) ^ 1];
        *(__nv_bfloat16*)(nb + b_addr(j0, n0)) = __float2bfloat16_rn(h00);
        *(__nv_bfloat16*)(nb + b_addr(j0, n1)) = __float2bfloat16_rn(h01);
        *(__nv_bfloat16*)(nb + b_addr(j1, n0)) = __float2bfloat16_rn(h10);
        *(__nv_bfloat16*)(nb + b_addr(j1, n1)) = __float2bfloat16_rn(h11);

        __syncthreads();
    }

    if (write_final) {
        float* fh = dout + (size_t)Bn * Ln * Vn;
        fh[(B0 + n0) * Hn + j0] = h00;
        fh[(B0 + n1) * Hn + j0] = h01;
        fh[(B0 + n0) * Hn + j1] = h10;
        fh[(B0 + n1) * Hn + j1] = h11;
    }
}

// ---------------- logits GEMM on fp16 HMMA (mma.sync m16n8k16) -------------
// logits[r][v] = sum_k hout[r][k] * fcw[v][k] + fcb[v]
// 148 persistent CTAs x 256 threads (8 warps). Tile = 64 rows x 64 V x K=256.
// Warp w owns n-strip [8w, 8w+8) x 4 m16 tiles. fp16 operands, fp32 acc.
// h tile double-buffered in smem, filled by cp.async (prefetch next tile
// during current tile's MMAs). A fragments via ldmatrix.x4.
#define FTW 264                       // halves per fT row (pad: 8)
#define HSW 264                       // halves per hsm row (pad: 8)
#define HS_TILE (64 * HSW)            // halves per h buffer
#define FT_BYTES (64 * FTW * 2)       // 33792
#define LOG_SMEM (FT_BYTES + 2 * HS_TILE * 2)

#define CP_ASYNC16(dst, src) \
    asm volatile("cp.async.cg.shared.global [%0], [%1], 16;" :: "r"(dst), "l"(src) : "memory")
#define CP_COMMIT() asm volatile("cp.async.commit_group;" ::: "memory")
#define CP_WAIT0()  asm volatile("cp.async.wait_group 0;" ::: "memory")

__global__ void __launch_bounds__(256, 1) k_logits(const float* __restrict__ fcw,
        const float* __restrict__ fcb, float* __restrict__ out) {
    extern __shared__ char smem[];
    __half* fT = (__half*)smem;                       // [64 v][264 k]
    const uint32_t hsm_u = smem_u32(smem) + FT_BYTES; // h buffers (u32 smem addr)
    const int tid = threadIdx.x;
    const int wid = tid >> 5, lane = tid & 31;
    const int g = lane >> 2, tt = lane & 3;
    const int nb = wid * 8;

    // fT[v][k] = fp16(fcw[v][k]) — coalesced LDG + STS.16
    for (int p = tid; p < Vn * Hn; p += 256) {
        int v = p >> 8, k = p & 255;
        fT[v * FTW + k] = __float2half_rn(fcw[v * Hn + k]);
    }
    const float2 bias = make_float2(fcb[nb + 2 * tt], fcb[nb + 2 * tt + 1]);

    // ldmatrix lane row assignment (within a 16x16 A tile)
    const int rit  = (lane & 7) + ((lane >> 3) & 1) * 8;   // row in tile
    const int kblk = (lane >> 4) * 8;                      // k sub-block

    const int ntiles = (Bn * Ln) / 64;      // 4096
    const int stride = gridDim.x;

    // prologue: prefetch my first tile into buffer 0
    int tile = blockIdx.x;
    if (tile < ntiles) {
        const char* src = (const char*)(g_hout + (size_t)tile * 64 * Hn);
        #pragma unroll
        for (int i = 0; i < 8; i++) {
            int p = tid + i * 256, row = p >> 5, c = p & 31;
            CP_ASYNC16(hsm_u + row * (HSW * 2) + c * 16, src + row * 512 + c * 16);
        }
    }
    CP_COMMIT();
    __syncthreads();   // fT visible

    int buf = 0;
    for (; tile < ntiles; tile += stride) {
        CP_WAIT0();
        __syncthreads();

        // prefetch next tile into the other buffer (overlaps MMAs below)
        int next = tile + stride;
        if (next < ntiles) {
            const char* src = (const char*)(g_hout + (size_t)next * 64 * Hn);
            uint32_t dst = hsm_u + (uint32_t)(buf ^ 1) * (HS_TILE * 2);
            #pragma unroll
            for (int i = 0; i < 8; i++) {
                int p = tid + i * 256, row = p >> 5, c = p & 31;
                CP_ASYNC16(dst + row * (HSW * 2) + c * 16, src + row * 512 + c * 16);
            }
        }
        CP_COMMIT();

        const uint32_t hb = hsm_u + (uint32_t)buf * (HS_TILE * 2);
        const uint32_t lmbase = hb + (uint32_t)rit * (HSW * 2) + (uint32_t)kblk * 2;
        const __half* ftr = fT + (nb + g) * FTW + 2 * tt;

        float c[4][4];
        #pragma unroll
        for (int mt = 0; mt < 4; mt++)
            #pragma unroll
            for (int e = 0; e < 4; e++) c[mt][e] = 0.f;

        #pragma unroll 4
        for (int ks = 0; ks < 16; ks++) {
            int k0 = 16 * ks;
            uint32_t b0 = *(const uint32_t*)(ftr + k0);
            uint32_t b1 = *(const uint32_t*)(ftr + k0 + 8);
            #pragma unroll
            for (int mt = 0; mt < 4; mt++) {
                uint32_t a0, a1, a2, a3;
                uint32_t addr = lmbase + (uint32_t)mt * (16 * HSW * 2) + (uint32_t)k0 * 2;
                asm volatile("ldmatrix.sync.aligned.m8n8.x4.shared.b16 "
                             "{%0,%1,%2,%3}, [%4];"
                             : "=r"(a0), "=r"(a1), "=r"(a2), "=r"(a3) : "r"(addr));
                asm volatile(
                    "mma.sync.aligned.m16n8k16.row.col.f32.f16.f16.f32 "
                    "{%0,%1,%2,%3}, {%4,%5,%6,%7}, {%8,%9}, {%0,%1,%2,%3};"
                    : "+f"(c[mt][0]), "+f"(c[mt][1]), "+f"(c[mt][2]), "+f"(c[mt][3])
                    : "r"(a0), "r"(a1), "r"(a2), "r"(a3), "r"(b0), "r"(b1));
            }
        }

        #pragma unroll
        for (int mt = 0; mt < 4; mt++) {
            int r0 = mt * 16 + g;
            size_t o0 = ((size_t)tile * 64 + r0) * 64 + nb + 2 * tt;
            *(float2*)(out + o0) = make_float2(c[mt][0] + bias.x, c[mt][1] + bias.y);
            *(float2*)(out + o0 + 8 * 64) = make_float2(c[mt][2] + bias.x, c[mt][3] + bias.y);
        }
        buf ^= 1;
    }
}

// ---------------- launch ----------------
extern "C" void kernel_launch(void* const* d_in, const int* in_sizes, int n_in,
                              void* d_out, int out_size) {
    const void*  x      = d_in[0];
    const float* hidden = (const float*)d_in[1];
    const float* emb    = (const float*)d_in[2];
    const float* We     = (const float*)d_in[3];
    const float* be     = (const float*)d_in[4];
    const float* Wh     = (const float*)d_in[5];
    const float* bhp    = (const float*)d_in[6];
    const float* fcw    = (const float*)d_in[7];
    const float* fcb    = (const float*)d_in[8];
    float* out = (float*)d_out;

    cudaFuncSetAttribute(k_logits, cudaFuncAttributeMaxDynamicSharedMemorySize, LOG_SMEM);

    k_reset<<<1, 1>>>();
    k_detect<<<(Bn * Ln / 2 + 255) / 256, 256>>>((const unsigned int*)x);
    k_proj<<<Vn, Hn>>>(emb, We, be);

    int write_final = (out_size >= Bn * Ln * Vn + Bn * Hn) ? 1 : 0;
    k_rnn<<<NCTA, 512>>>(x, hidden, Wh, bhp, out, write_final);
    k_logits<<<148, 256, LOG_SMEM>>>(fcw, fcb, out);
}

// round 16
// speedup vs baseline: 2.0902x; 1.0012x over previous
#include <cuda_runtime.h>
#include <cuda_fp16.h>
#include <cuda_bf16.h>
#include <cstdint>

#define Bn 256
#define Ln 1024
#define En 128
#define Hn 256
#define Vn 64
#define NB 8                  // batches per rnn CTA (MMA N)
#define NRNN (Bn / NB)        // 32 rnn CTAs
#define NLOG 116              // logits CTAs (148 total)
#define NTILES ((Bn * Ln) / 64)

// ---- device-global scratch (no allocations allowed) ----
__device__ float  g_proj[Vn * Hn];                   // token -> x_proj row (b_e folded in)
__device__ __half g_hout[(size_t)Bn * Ln * Hn];      // all hidden states, fp16, 134MB
__device__ int    g_x_is32;
__device__ int    g_prog[NRNN];                      // steps completed per rnn CTA

__device__ __forceinline__ float tanh_hw(float x) {
    float r;
    asm("tanh.approx.f32 %0, %1;" : "=f"(r) : "f"(x));
    return r;
}
__device__ __forceinline__ uint32_t smem_u32(const void* p) {
    uint32_t a;
    asm("{ .reg .u64 t; cvta.to.shared.u64 t, %1; cvt.u32.u64 %0, t; }" : "=r"(a) : "l"(p));
    return a;
}
__device__ __forceinline__ int ld_acq(const int* p) {
    int v;
    asm volatile("ld.global.acquire.gpu.b32 %0, [%1];" : "=r"(v) : "l"(p) : "memory");
    return v;
}

// ---------------- setup kernels ----------------
__global__ void k_reset() {
    g_x_is32 = 0;
    for (int i = 0; i < NRNN; i++) g_prog[i] = 0;
}

__global__ void k_detect(const unsigned int* __restrict__ xw) {
    int i = blockIdx.x * blockDim.x + threadIdx.x;
    int idx = 2 * i + 1;
    if (idx < Bn * Ln) {
        if (xw[idx] != 0u) g_x_is32 = 1;   // int64 high halves all zero (vals 0..63)
    }
}

__global__ void k_proj(const float* __restrict__ emb, const float* __restrict__ We,
                       const float* __restrict__ be) {
    __shared__ float es[En];
    int v = blockIdx.x, j = threadIdx.x;
    if (j < En) es[j] = emb[v * En + j];
    __syncthreads();
    float acc = 0.f;
    #pragma unroll
    for (int e = 0; e < En; e++) acc = fmaf(es[e], We[j * En + e], acc);
    g_proj[v * Hn + j] = acc + be[j];
}

// ---------------- shared helpers ----------------
__device__ __forceinline__ uint32_t b_addr(int j, int n) {
    return (uint32_t)((j >> 4) * 256 + (((n << 2) | ((j & 7) >> 1)) << 3)
                      + (((j >> 3) & 1) << 2) + ((j & 1) << 1));
}
__device__ __forceinline__ unsigned bf2(float a, float b) {
    __nv_bfloat162 t = __floats2bfloat162_rn(a, b);
    return *(unsigned*)&t;
}

// logits smem layout
#define FTW 264                       // halves per fT row (pad: 8)
#define HSW 264                       // halves per hsm row (pad: 8)
#define HS_TILE (64 * HSW)            // halves per h buffer
#define FT_BYTES (64 * FTW * 2)       // 33792
#define FUSED_SMEM (FT_BYTES + 2 * HS_TILE * 2)   // 101376 (rnn uses first 8KB)

#define CP_ASYNC16(dst, src) \
    asm volatile("cp.async.cg.shared.global [%0], [%1], 16;" :: "r"(dst), "l"(src) : "memory")
#define CP_COMMIT() asm volatile("cp.async.commit_group;" ::: "memory")
#define CP_WAIT0()  asm volatile("cp.async.wait_group 0;" ::: "memory")

// ================= fused kernel: 32 rnn CTAs + 116 logits CTAs =============
__global__ void __launch_bounds__(512, 1) k_fused(const void* __restrict__ xraw,
        const float* __restrict__ hidden, const float* __restrict__ Wh,
        const float* __restrict__ bh, const float* __restrict__ fcw,
        const float* __restrict__ fcb, float* __restrict__ out, int write_final) {
    extern __shared__ __align__(16) char smem[];
    const int tid = threadIdx.x;
    const int wid = tid >> 5, lane = tid & 31;
    const int g = lane >> 2, tt = lane & 3;

    if (blockIdx.x < NRNN) {
        // ===================== RNN part (R15 structure) =====================
        char* bbuf = smem;                       // [2][4096] B-fragment buffers
        const int j0 = wid * 16 + g, j1 = j0 + 8;
        const int n0 = 2 * tt, n1 = n0 + 1;
        const int B0 = blockIdx.x * NB;
        const int is32 = g_x_is32;
        const int* x32       = (const int*)xraw;
        const long long* x64 = (const long long*)xraw;

        unsigned wf[16][4];
        #pragma unroll
        for (int kk = 0; kk < 16; kk++) {
            int k = kk * 16 + 2 * tt;
            float2 p0 = *(const float2*)(Wh + j0 * Hn + k);
            float2 p1 = *(const float2*)(Wh + j1 * Hn + k);
            float2 p2 = *(const float2*)(Wh + j0 * Hn + k + 8);
            float2 p3 = *(const float2*)(Wh + j1 * Hn + k + 8);
            wf[kk][0] = bf2(p0.x, p0.y);
            wf[kk][1] = bf2(p1.x, p1.y);
            wf[kk][2] = bf2(p2.x, p2.y);
            wf[kk][3] = bf2(p3.x, p3.y);
        }

        for (int p = tid; p < Hn * NB; p += 512) {
            int j = p >> 3, n = p & 7;
            float hv = hidden[(B0 + n) * Hn + j];
            *(__nv_bfloat16*)(bbuf + b_addr(j, n)) = __float2bfloat16_rn(hv);
        }

        const float bh0 = bh[j0], bh1 = bh[j1];
        size_t base = ((size_t)(B0 + n0) * Ln) * Hn + j0;
        const size_t NSTRIDE = (size_t)Ln * Hn;

        int tokA = is32 ? x32[(B0 + n0) * Ln] : (int)x64[(B0 + n0) * Ln];
        int tokB = is32 ? x32[(B0 + n1) * Ln] : (int)x64[(B0 + n1) * Ln];

        __syncthreads();

        float h00 = 0.f, h01 = 0.f, h10 = 0.f, h11 = 0.f;
        for (int t = 0; t < Ln; t++) {
            float c0 = g_proj[tokA * Hn + j0] + bh0;
            float c1 = g_proj[tokB * Hn + j0] + bh0;
            float c2 = g_proj[tokA * Hn + j1] + bh1;
            float c3 = g_proj[tokB * Hn + j1] + bh1;

            if (t + 1 < Ln) {
                tokA = is32 ? x32[(B0 + n0) * Ln + t + 1] : (int)x64[(B0 + n0) * Ln + t + 1];
                tokB = is32 ? x32[(B0 + n1) * Ln + t + 1] : (int)x64[(B0 + n1) * Ln + t + 1];
            }

            const char* cb = bbuf + (t & 1) * 4096;
            #pragma unroll
            for (int kk = 0; kk < 16; kk++) {
                unsigned long long bb = *(const unsigned long long*)(cb + kk * 256 + lane * 8);
                unsigned b0 = (unsigned)bb, b1 = (unsigned)(bb >> 32);
                asm volatile(
                    "mma.sync.aligned.m16n8k16.row.col.f32.bf16.bf16.f32 "
                    "{%0,%1,%2,%3}, {%4,%5,%6,%7}, {%8,%9}, {%0,%1,%2,%3};"
                    : "+f"(c0), "+f"(c1), "+f"(c2), "+f"(c3)
                    : "r"(wf[kk][0]), "r"(wf[kk][1]), "r"(wf[kk][2]), "r"(wf[kk][3]),
                      "r"(b0), "r"(b1));
            }

            h00 = tanh_hw(c0);
            h01 = tanh_hw(c1);
            h10 = tanh_hw(c2);
            h11 = tanh_hw(c3);

            g_hout[base]               = __float2half_rn(h00);
            g_hout[base + NSTRIDE]     = __float2half_rn(h01);
            g_hout[base + 8]           = __float2half_rn(h10);
            g_hout[base + NSTRIDE + 8] = __float2half_rn(h11);
            base += Hn;

            char* nbuf = bbuf + ((t & 1) ^ 1) * 4096;
            *(__nv_bfloat16*)(nbuf + b_addr(j0, n0)) = __float2bfloat16_rn(h00);
            *(__nv_bfloat16*)(nbuf + b_addr(j0, n1)) = __float2bfloat16_rn(h01);
            *(__nv_bfloat16*)(nbuf + b_addr(j1, n0)) = __float2bfloat16_rn(h10);
            *(__nv_bfloat16*)(nbuf + b_addr(j1, n1)) = __float2bfloat16_rn(h11);

            __syncthreads();

            // publish progress every 64 steps (release to gpu scope)
            if ((t & 63) == 63 && tid == 0) {
                asm volatile("fence.acq_rel.gpu;" ::: "memory");
                asm volatile("st.global.relaxed.gpu.b32 [%0], %1;"
                             :: "l"(&g_prog[blockIdx.x]), "r"(t + 1) : "memory");
            }
        }

        if (write_final) {
            float* fh = out + (size_t)Bn * Ln * Vn;
            fh[(B0 + n0) * Hn + j0] = h00;
            fh[(B0 + n1) * Hn + j0] = h01;
            fh[(B0 + n0) * Hn + j1] = h10;
            fh[(B0 + n1) * Hn + j1] = h11;
        }
    } else {
        // ===================== logits part (fp16 HMMA) ======================
        // tile i: batch b = i&255, chunk tc = i>>8 -> rows [b*Ln+64tc, +64).
        // Tile ready when g_prog[b>>3] >= 64(tc+1). tc-major order matches
        // production order; spin + cp.async double-buffer.
        const int cid = blockIdx.x - NRNN;
        __half* fT = (__half*)smem;                       // [64 v][264 k]
        const uint32_t hsm_u = smem_u32(smem) + FT_BYTES;
        const int nb = (wid & 7) * 8;
        const int mh = wid >> 3;                          // m-half 0/1

        for (int p = tid; p < Vn * Hn; p += 512) {
            int v = p >> 8, k = p & 255;
            fT[v * FTW + k] = __float2half_rn(fcw[v * Hn + k]);
        }
        const float2 bias = make_float2(fcb[nb + 2 * tt], fcb[nb + 2 * tt + 1]);

        const int rit  = (lane & 7) + ((lane >> 3) & 1) * 8;
        const int kblk = (lane >> 4) * 8;

        // prologue: wait for + prefetch my first tile
        int i = cid;
        if (i < NTILES) {
            int b = i & 255, tc = i >> 8, need = 64 * (tc + 1);
            while (ld_acq(&g_prog[b >> 3]) < need) __nanosleep(64);
            const char* src = (const char*)(g_hout + (size_t)(b * Ln + tc * 64) * Hn);
            #pragma unroll
            for (int it = 0; it < 4; it++) {
                int p = tid + it * 512, row = p >> 5, c16 = p & 31;
                CP_ASYNC16(hsm_u + row * (HSW * 2) + c16 * 16, src + row * 512 + c16 * 16);
            }
        }
        CP_COMMIT();
        __syncthreads();   // fT visible

        int buf = 0;
        for (; i < NTILES; i += NLOG) {
            CP_WAIT0();
            __syncthreads();

            // wait for + prefetch next tile (overlaps MMAs below)
            int nx = i + NLOG;
            if (nx < NTILES) {
                int b = nx & 255, tc = nx >> 8, need = 64 * (tc + 1);
                while (ld_acq(&g_prog[b >> 3]) < need) __nanosleep(64);
                const char* src = (const char*)(g_hout + (size_t)(b * Ln + tc * 64) * Hn);
                uint32_t dst = hsm_u + (uint32_t)(buf ^ 1) * (HS_TILE * 2);
                #pragma unroll
                for (int it = 0; it < 4; it++) {
                    int p = tid + it * 512, row = p >> 5, c16 = p & 31;
                    CP_ASYNC16(dst + row * (HSW * 2) + c16 * 16, src + row * 512 + c16 * 16);
                }
            }
            CP_COMMIT();

            const uint32_t hb = hsm_u + (uint32_t)buf * (HS_TILE * 2);
            const __half* ftr = fT + (nb + g) * FTW + 2 * tt;

            float c[2][4];
            #pragma unroll
            for (int mt = 0; mt < 2; mt++)
                #pragma unroll
                for (int e = 0; e < 4; e++) c[mt][e] = 0.f;

            #pragma unroll 4
            for (int ks = 0; ks < 16; ks++) {
                int k0 = 16 * ks;
                uint32_t b0 = *(const uint32_t*)(ftr + k0);
                uint32_t b1 = *(const uint32_t*)(ftr + k0 + 8);
                #pragma unroll
                for (int mt = 0; mt < 2; mt++) {
                    int row = mh * 32 + mt * 16 + rit;
                    uint32_t a0, a1, a2, a3;
                    uint32_t addr = hb + (uint32_t)row * (HSW * 2)
                                  + (uint32_t)(kblk + k0) * 2;
                    asm volatile("ldmatrix.sync.aligned.m8n8.x4.shared.b16 "
                                 "{%0,%1,%2,%3}, [%4];"
                                 : "=r"(a0), "=r"(a1), "=r"(a2), "=r"(a3) : "r"(addr));
                    asm volatile(
                        "mma.sync.aligned.m16n8k16.row.col.f32.f16.f16.f32 "
                        "{%0,%1,%2,%3}, {%4,%5,%6,%7}, {%8,%9}, {%0,%1,%2,%3};"
                        : "+f"(c[mt][0]), "+f"(c[mt][1]), "+f"(c[mt][2]), "+f"(c[mt][3])
                        : "r"(a0), "r"(a1), "r"(a2), "r"(a3), "r"(b0), "r"(b1));
                }
            }

            size_t rowbase = (size_t)((i & 255) * Ln + (i >> 8) * 64);
            #pragma unroll
            for (int mt = 0; mt < 2; mt++) {
                int r0 = mh * 32 + mt * 16 + g;
                size_t o0 = (rowbase + r0) * 64 + nb + 2 * tt;
                *(float2*)(out + o0) = make_float2(c[mt][0] + bias.x, c[mt][1] + bias.y);
                *(float2*)(out + o0 + 8 * 64) = make_float2(c[mt][2] + bias.x, c[mt][3] + bias.y);
            }
            buf ^= 1;
        }
    }
}

// ---------------- launch ----------------
extern "C" void kernel_launch(void* const* d_in, const int* in_sizes, int n_in,
                              void* d_out, int out_size) {
    const void*  x      = d_in[0];
    const float* hidden = (const float*)d_in[1];
    const float* emb    = (const float*)d_in[2];
    const float* We     = (const float*)d_in[3];
    const float* be     = (const float*)d_in[4];
    const float* Wh     = (const float*)d_in[5];
    const float* bhp    = (const float*)d_in[6];
    const float* fcw    = (const float*)d_in[7];
    const float* fcb    = (const float*)d_in[8];
    float* out = (float*)d_out;

    cudaFuncSetAttribute(k_fused, cudaFuncAttributeMaxDynamicSharedMemorySize, FUSED_SMEM);

    k_reset<<<1, 1>>>();
    k_detect<<<(Bn * Ln / 2 + 255) / 256, 256>>>((const unsigned int*)x);
    k_proj<<<Vn, Hn>>>(emb, We, be);

    int write_final = (out_size >= Bn * Ln * Vn + Bn * Hn) ? 1 : 0;
    k_fused<<<NRNN + NLOG, 512, FUSED_SMEM>>>(x, hidden, Wh, bhp, fcw, fcb,
                                              out, write_final);
}

// round 17
// speedup vs baseline: 2.2419x; 1.0725x over previous
#include <cuda_runtime.h>
#include <cuda_fp16.h>
#include <cuda_bf16.h>
#include <cstdint>

#define Bn 256
#define Ln 1024
#define En 128
#define Hn 256
#define Vn 64
#define NB 8                  // batches per rnn CTA (MMA N)
#define NRNN (Bn / NB)        // 32 rnn CTAs
#define NLOG 116              // logits CTAs (148 total)
#define NTILES ((Bn * Ln) / 64)

// ---- device-global scratch (no allocations allowed) ----
__device__ float  g_proj[Vn * Hn];                   // token -> x_proj row (b_e folded in)
__device__ __half g_hout[(size_t)Bn * Ln * Hn];      // all hidden states, fp16, 134MB
__device__ int    g_x_is32;
__device__ int    g_prog[NRNN];                      // steps completed per rnn CTA

__device__ __forceinline__ uint32_t smem_u32(const void* p) {
    uint32_t a;
    asm("{ .reg .u64 t; cvta.to.shared.u64 t, %1; cvt.u32.u64 %0, t; }" : "=r"(a) : "l"(p));
    return a;
}
__device__ __forceinline__ int ld_acq(const int* p) {
    int v;
    asm volatile("ld.global.acquire.gpu.b32 %0, [%1];" : "=r"(v) : "l"(p) : "memory");
    return v;
}
__device__ __forceinline__ unsigned hadd2(unsigned a, unsigned b) {
    unsigned r;
    asm("add.rn.f16x2 %0, %1, %2;" : "=r"(r) : "r"(a), "r"(b));
    return r;
}
__device__ __forceinline__ unsigned tanh2(unsigned a) {
    unsigned r;
    asm("tanh.approx.f16x2 %0, %1;" : "=r"(r) : "r"(a));
    return r;
}
__device__ __forceinline__ unsigned h2pack(float a, float b) {
    __half2 t = __floats2half2_rn(a, b);
    return *(unsigned*)&t;
}

// ---------------- setup kernels ----------------
__global__ void k_reset() {
    g_x_is32 = 0;
    for (int i = 0; i < NRNN; i++) g_prog[i] = 0;
}

__global__ void k_detect(const unsigned int* __restrict__ xw) {
    int i = blockIdx.x * blockDim.x + threadIdx.x;
    int idx = 2 * i + 1;
    if (idx < Bn * Ln) {
        if (xw[idx] != 0u) g_x_is32 = 1;   // int64 high halves all zero (vals 0..63)
    }
}

__global__ void k_proj(const float* __restrict__ emb, const float* __restrict__ We,
                       const float* __restrict__ be) {
    __shared__ float es[En];
    int v = blockIdx.x, j = threadIdx.x;
    if (j < En) es[j] = emb[v * En + j];
    __syncthreads();
    float acc = 0.f;
    #pragma unroll
    for (int e = 0; e < En; e++) acc = fmaf(es[e], We[j * En + e], acc);
    g_proj[v * Hn + j] = acc + be[j];
}

// ---------------- shared helpers ----------------
__device__ __forceinline__ uint32_t b_addr(int j, int n) {
    return (uint32_t)((j >> 4) * 256 + (((n << 2) | ((j & 7) >> 1)) << 3)
                      + (((j >> 3) & 1) << 2) + ((j & 1) << 1));
}

// logits smem layout
#define FTW 264                       // halves per fT row (pad: 8)
#define HSW 264                       // halves per hsm row (pad: 8)
#define HS_TILE (64 * HSW)            // halves per h buffer
#define FT_BYTES (64 * FTW * 2)       // 33792
#define FUSED_SMEM (FT_BYTES + 2 * HS_TILE * 2)   // 101376 (rnn uses first 8KB)

#define CP_ASYNC16(dst, src) \
    asm volatile("cp.async.cg.shared.global [%0], [%1], 16;" :: "r"(dst), "l"(src) : "memory")
#define CP_COMMIT() asm volatile("cp.async.commit_group;" ::: "memory")
#define CP_WAIT0()  asm volatile("cp.async.wait_group 0;" ::: "memory")

// ================= fused kernel: 32 rnn CTAs + 116 logits CTAs =============
__global__ void __launch_bounds__(512, 1) k_fused(const void* __restrict__ xraw,
        const float* __restrict__ hidden, const float* __restrict__ Wh,
        const float* __restrict__ bh, const float* __restrict__ fcw,
        const float* __restrict__ fcb, float* __restrict__ out, int write_final) {
    extern __shared__ __align__(16) char smem[];
    const int tid = threadIdx.x;
    const int wid = tid >> 5, lane = tid & 31;
    const int g = lane >> 2, tt = lane & 3;

    if (blockIdx.x < NRNN) {
        // ============== RNN: fp16 inputs + fp16 accumulators ==============
        char* bbuf = smem;                       // [2][4096] fp16 B-fragment buffers
        const int j0 = wid * 16 + g, j1 = j0 + 8;
        const int n0 = 2 * tt, n1 = n0 + 1;
        const int B0 = blockIdx.x * NB;
        const int is32 = g_x_is32;
        const int* x32       = (const int*)xraw;
        const long long* x64 = (const long long*)xraw;

        // W_h as fp16 A fragments in registers
        unsigned wf[16][4];
        #pragma unroll
        for (int kk = 0; kk < 16; kk++) {
            int k = kk * 16 + 2 * tt;
            float2 p0 = *(const float2*)(Wh + j0 * Hn + k);
            float2 p1 = *(const float2*)(Wh + j1 * Hn + k);
            float2 p2 = *(const float2*)(Wh + j0 * Hn + k + 8);
            float2 p3 = *(const float2*)(Wh + j1 * Hn + k + 8);
            wf[kk][0] = h2pack(p0.x, p0.y);
            wf[kk][1] = h2pack(p1.x, p1.y);
            wf[kk][2] = h2pack(p2.x, p2.y);
            wf[kk][3] = h2pack(p3.x, p3.y);
        }

        // initial B fill from hidden (fp32 -> fp16, fragment layout)
        for (int p = tid; p < Hn * NB; p += 512) {
            int j = p >> 3, n = p & 7;
            float hv = hidden[(B0 + n) * Hn + j];
            *(__half*)(bbuf + b_addr(j, n)) = __float2half_rn(hv);
        }

        const float bh0 = bh[j0], bh1 = bh[j1];
        size_t base = ((size_t)(B0 + n0) * Ln) * Hn + j0;
        const size_t NSTRIDE = (size_t)Ln * Hn;

        int tokA = is32 ? x32[(B0 + n0) * Ln] : (int)x64[(B0 + n0) * Ln];
        int tokB = is32 ? x32[(B0 + n1) * Ln] : (int)x64[(B0 + n1) * Ln];

        __syncthreads();

        unsigned t0 = 0u, t1 = 0u;   // final tanh results (packed n0|n1)
        for (int t = 0; t < Ln; t++) {
            // group A seeded with xp + bh (packed); group B zero
            unsigned dA0 = h2pack(g_proj[tokA * Hn + j0] + bh0,
                                  g_proj[tokB * Hn + j0] + bh0);
            unsigned dA1 = h2pack(g_proj[tokA * Hn + j1] + bh1,
                                  g_proj[tokB * Hn + j1] + bh1);
            unsigned dB0 = 0u, dB1 = 0u;

            if (t + 1 < Ln) {
                tokA = is32 ? x32[(B0 + n0) * Ln + t + 1] : (int)x64[(B0 + n0) * Ln + t + 1];
                tokB = is32 ? x32[(B0 + n1) * Ln + t + 1] : (int)x64[(B0 + n1) * Ln + t + 1];
            }

            const char* cb = bbuf + (t & 1) * 4096;
            #pragma unroll
            for (int kk = 0; kk < 16; kk++) {
                unsigned long long bb = *(const unsigned long long*)(cb + kk * 256 + lane * 8);
                unsigned b0 = (unsigned)bb, b1 = (unsigned)(bb >> 32);
                if (kk & 1) {
                    asm volatile(
                        "mma.sync.aligned.m16n8k16.row.col.f16.f16.f16.f16 "
                        "{%0,%1}, {%2,%3,%4,%5}, {%6,%7}, {%0,%1};"
                        : "+r"(dB0), "+r"(dB1)
                        : "r"(wf[kk][0]), "r"(wf[kk][1]), "r"(wf[kk][2]), "r"(wf[kk][3]),
                          "r"(b0), "r"(b1));
                } else {
                    asm volatile(
                        "mma.sync.aligned.m16n8k16.row.col.f16.f16.f16.f16 "
                        "{%0,%1}, {%2,%3,%4,%5}, {%6,%7}, {%0,%1};"
                        : "+r"(dA0), "+r"(dA1)
                        : "r"(wf[kk][0]), "r"(wf[kk][1]), "r"(wf[kk][2]), "r"(wf[kk][3]),
                          "r"(b0), "r"(b1));
                }
            }

            t0 = tanh2(hadd2(dA0, dB0));   // rows j0: (n0, n1)
            t1 = tanh2(hadd2(dA1, dB1));   // rows j1: (n0, n1)
            __half2 h2a = *(__half2*)&t0;
            __half2 h2b = *(__half2*)&t1;

            // fp16 hidden states to gmem
            g_hout[base]               = __low2half(h2a);
            g_hout[base + NSTRIDE]     = __high2half(h2a);
            g_hout[base + 8]           = __low2half(h2b);
            g_hout[base + NSTRIDE + 8] = __high2half(h2b);
            base += Hn;

            // fp16 h into the other buffer (next step's B operand)
            char* nbuf = bbuf + ((t & 1) ^ 1) * 4096;
            *(__half*)(nbuf + b_addr(j0, n0)) = __low2half(h2a);
            *(__half*)(nbuf + b_addr(j0, n1)) = __high2half(h2a);
            *(__half*)(nbuf + b_addr(j1, n0)) = __low2half(h2b);
            *(__half*)(nbuf + b_addr(j1, n1)) = __high2half(h2b);

            __syncthreads();

            // publish progress every 64 steps (release to gpu scope)
            if ((t & 63) == 63 && tid == 0) {
                asm volatile("fence.acq_rel.gpu;" ::: "memory");
                asm volatile("st.global.relaxed.gpu.b32 [%0], %1;"
                             :: "l"(&g_prog[blockIdx.x]), "r"(t + 1) : "memory");
            }
        }

        if (write_final) {
            __half2 h2a = *(__half2*)&t0;
            __half2 h2b = *(__half2*)&t1;
            float* fh = out + (size_t)Bn * Ln * Vn;
            fh[(B0 + n0) * Hn + j0] = __half2float(__low2half(h2a));
            fh[(B0 + n1) * Hn + j0] = __half2float(__high2half(h2a));
            fh[(B0 + n0) * Hn + j1] = __half2float(__low2half(h2b));
            fh[(B0 + n1) * Hn + j1] = __half2float(__high2half(h2b));
        }
    } else {
        // ===================== logits part (fp16 HMMA) ======================
        const int cid = blockIdx.x - NRNN;
        __half* fT = (__half*)smem;                       // [64 v][264 k]
        const uint32_t hsm_u = smem_u32(smem) + FT_BYTES;
        const int nb = (wid & 7) * 8;
        const int mh = wid >> 3;                          // m-half 0/1

        for (int p = tid; p < Vn * Hn; p += 512) {
            int v = p >> 8, k = p & 255;
            fT[v * FTW + k] = __float2half_rn(fcw[v * Hn + k]);
        }
        const float2 bias = make_float2(fcb[nb + 2 * tt], fcb[nb + 2 * tt + 1]);

        const int rit  = (lane & 7) + ((lane >> 3) & 1) * 8;
        const int kblk = (lane >> 4) * 8;

        // prologue: wait for + prefetch my first tile
        int i = cid;
        if (i < NTILES) {
            int b = i & 255, tc = i >> 8, need = 64 * (tc + 1);
            while (ld_acq(&g_prog[b >> 3]) < need) __nanosleep(64);
            const char* src = (const char*)(g_hout + (size_t)(b * Ln + tc * 64) * Hn);
            #pragma unroll
            for (int it = 0; it < 4; it++) {
                int p = tid + it * 512, row = p >> 5, c16 = p & 31;
                CP_ASYNC16(hsm_u + row * (HSW * 2) + c16 * 16, src + row * 512 + c16 * 16);
            }
        }
        CP_COMMIT();
        __syncthreads();   // fT visible

        int buf = 0;
        for (; i < NTILES; i += NLOG) {
            CP_WAIT0();
            __syncthreads();

            int nx = i + NLOG;
            if (nx < NTILES) {
                int b = nx & 255, tc = nx >> 8, need = 64 * (tc + 1);
                while (ld_acq(&g_prog[b >> 3]) < need) __nanosleep(64);
                const char* src = (const char*)(g_hout + (size_t)(b * Ln + tc * 64) * Hn);
                uint32_t dst = hsm_u + (uint32_t)(buf ^ 1) * (HS_TILE * 2);
                #pragma unroll
                for (int it = 0; it < 4; it++) {
                    int p = tid + it * 512, row = p >> 5, c16 = p & 31;
                    CP_ASYNC16(dst + row * (HSW * 2) + c16 * 16, src + row * 512 + c16 * 16);
                }
            }
            CP_COMMIT();

            const uint32_t hb = hsm_u + (uint32_t)buf * (HS_TILE * 2);
            const __half* ftr = fT + (nb + g) * FTW + 2 * tt;

            float c[2][4];
            #pragma unroll
            for (int mt = 0; mt < 2; mt++)
                #pragma unroll
                for (int e = 0; e < 4; e++) c[mt][e] = 0.f;

            #pragma unroll 4
            for (int ks = 0; ks < 16; ks++) {
                int k0 = 16 * ks;
                uint32_t b0 = *(const uint32_t*)(ftr + k0);
                uint32_t b1 = *(const uint32_t*)(ftr + k0 + 8);
                #pragma unroll
                for (int mt = 0; mt < 2; mt++) {
                    int row = mh * 32 + mt * 16 + rit;
                    uint32_t a0, a1, a2, a3;
                    uint32_t addr = hb + (uint32_t)row * (HSW * 2)
                                  + (uint32_t)(kblk + k0) * 2;
                    asm volatile("ldmatrix.sync.aligned.m8n8.x4.shared.b16 "
                                 "{%0,%1,%2,%3}, [%4];"
                                 : "=r"(a0), "=r"(a1), "=r"(a2), "=r"(a3) : "r"(addr));
                    asm volatile(
                        "mma.sync.aligned.m16n8k16.row.col.f32.f16.f16.f32 "
                        "{%0,%1,%2,%3}, {%4,%5,%6,%7}, {%8,%9}, {%0,%1,%2,%3};"
                        : "+f"(c[mt][0]), "+f"(c[mt][1]), "+f"(c[mt][2]), "+f"(c[mt][3])
                        : "r"(a0), "r"(a1), "r"(a2), "r"(a3), "r"(b0), "r"(b1));
                }
            }

            size_t rowbase = (size_t)((i & 255) * Ln + (i >> 8) * 64);
            #pragma unroll
            for (int mt = 0; mt < 2; mt++) {
                int r0 = mh * 32 + mt * 16 + g;
                size_t o0 = (rowbase + r0) * 64 + nb + 2 * tt;
                *(float2*)(out + o0) = make_float2(c[mt][0] + bias.x, c[mt][1] + bias.y);
                *(float2*)(out + o0 + 8 * 64) = make_float2(c[mt][2] + bias.x, c[mt][3] + bias.y);
            }
            buf ^= 1;
        }
    }
}

// ---------------- launch ----------------
extern "C" void kernel_launch(void* const* d_in, const int* in_sizes, int n_in,
                              void* d_out, int out_size) {
    const void*  x      = d_in[0];
    const float* hidden = (const float*)d_in[1];
    const float* emb    = (const float*)d_in[2];
    const float* We     = (const float*)d_in[3];
    const float* be     = (const float*)d_in[4];
    const float* Wh     = (const float*)d_in[5];
    const float* bhp    = (const float*)d_in[6];
    const float* fcw    = (const float*)d_in[7];
    const float* fcb    = (const float*)d_in[8];
    float* out = (float*)d_out;

    cudaFuncSetAttribute(k_fused, cudaFuncAttributeMaxDynamicSharedMemorySize, FUSED_SMEM);

    k_reset<<<1, 1>>>();
    k_detect<<<(Bn * Ln / 2 + 255) / 256, 256>>>((const unsigned int*)x);
    k_proj<<<Vn, Hn>>>(emb, We, be);

    int write_final = (out_size >= Bn * Ln * Vn + Bn * Hn) ? 1 : 0;
    k_fused<<<NRNN + NLOG, 512, FUSED_SMEM>>>(x, hidden, Wh, bhp, fcw, fcb,
                                              out, write_final);
}